// round 1
// baseline (speedup 1.0000x reference)
#include <cuda_runtime.h>

#define D 64
#define NMAX 50000

// Scratch (device globals — no allocation allowed in kernel_launch).
__device__ float g_m[NMAX * D];  // per-node message table
__device__ float g_z[NMAX * D];  // segment-sum accumulator

// ---------------------------------------------------------------------------
// Zero the accumulator (float4 stores).
// ---------------------------------------------------------------------------
__global__ void zero_kernel(float4* __restrict__ z, int n4) {
    int i = blockIdx.x * blockDim.x + threadIdx.x;
    if (i < n4) z[i] = make_float4(0.f, 0.f, 0.f, 0.f);
}

// ---------------------------------------------------------------------------
// Fused 2-layer MLP: out = relu(relu(in @ W1 + b1) @ W2 + b2)
// Warp-per-node. Weights staged in SMEM (32.5 KB). x row held 2 floats/lane,
// broadcast via shfl; each lane produces output elements 2*lane, 2*lane+1.
// ---------------------------------------------------------------------------
__global__ __launch_bounds__(256) void mlp2_kernel(
    const float* __restrict__ in,
    const float* __restrict__ W1, const float* __restrict__ b1,
    const float* __restrict__ W2, const float* __restrict__ b2,
    float* __restrict__ out, int n)
{
    __shared__ float sW1[D * D];
    __shared__ float sW2[D * D];
    __shared__ float sb1[D];
    __shared__ float sb2[D];

    for (int i = threadIdx.x; i < D * D; i += blockDim.x) {
        sW1[i] = W1[i];
        sW2[i] = W2[i];
    }
    if (threadIdx.x < D) {
        sb1[threadIdx.x] = b1[threadIdx.x];
        sb2[threadIdx.x] = b2[threadIdx.x];
    }
    __syncthreads();

    const int warp = threadIdx.x >> 5;
    const int lane = threadIdx.x & 31;
    const int node = blockIdx.x * 8 + warp;
    if (node >= n) return;

    const float* row = in + (size_t)node * D;
    const float x0 = row[lane];
    const float x1 = row[lane + 32];

    // Layer 1: h1[j] = relu(sum_k x[k] * W1[k*D + j] + b1[j]),
    // lane computes j = 2*lane and 2*lane+1 (LDS.64, conflict-free).
    float a0 = sb1[2 * lane];
    float a1 = sb1[2 * lane + 1];
#pragma unroll
    for (int k = 0; k < 32; k++) {
        const float xk = __shfl_sync(0xffffffffu, x0, k);
        const float2 w = *(const float2*)&sW1[k * D + 2 * lane];
        a0 = fmaf(xk, w.x, a0);
        a1 = fmaf(xk, w.y, a1);
    }
#pragma unroll
    for (int k = 0; k < 32; k++) {
        const float xk = __shfl_sync(0xffffffffu, x1, k);
        const float2 w = *(const float2*)&sW1[(k + 32) * D + 2 * lane];
        a0 = fmaf(xk, w.x, a0);
        a1 = fmaf(xk, w.y, a1);
    }
    a0 = fmaxf(a0, 0.f);
    a1 = fmaxf(a1, 0.f);

    // Layer 2: h1[k] lives on lane k>>1, element k&1.
    float c0 = sb2[2 * lane];
    float c1v = sb2[2 * lane + 1];
#pragma unroll
    for (int k = 0; k < 64; k++) {
        const float hk = __shfl_sync(0xffffffffu, (k & 1) ? a1 : a0, k >> 1);
        const float2 w = *(const float2*)&sW2[k * D + 2 * lane];
        c0 = fmaf(hk, w.x, c0);
        c1v = fmaf(hk, w.y, c1v);
    }
    c0 = fmaxf(c0, 0.f);
    c1v = fmaxf(c1v, 0.f);

    float2 o;
    o.x = c0;
    o.y = c1v;
    *(float2*)&out[(size_t)node * D + 2 * lane] = o;
}

// ---------------------------------------------------------------------------
// Scatter-add: z[dst[e]] += m[src[e]] for all edges.
// 16 threads per edge; each thread moves one float4 (coalesced 256B per edge)
// and issues one vectorized reduction (red.global.add.v4.f32, sm_90+).
// ---------------------------------------------------------------------------
__global__ __launch_bounds__(256) void scatter_kernel(
    const int* __restrict__ src, const int* __restrict__ dst, int e)
{
    const long long idx = (long long)blockIdx.x * blockDim.x + threadIdx.x;
    const int edge = (int)(idx >> 4);
    const int c = (int)(idx & 15);
    if (edge >= e) return;

    const int s = src[edge];
    const int d = dst[edge];

    const float4 v = ((const float4*)g_m)[s * 16 + c];
    float* addr = g_z + (size_t)d * D + c * 4;
    asm volatile("red.global.add.v4.f32 [%0], {%1,%2,%3,%4};"
                 :: "l"(addr), "f"(v.x), "f"(v.y), "f"(v.z), "f"(v.w)
                 : "memory");
}

// ---------------------------------------------------------------------------
extern "C" void kernel_launch(void* const* d_in, const int* in_sizes, int n_in,
                              void* d_out, int out_size) {
    const float* y  = (const float*)d_in[0];
    const int*   src = (const int*)d_in[1];
    const int*   dst = (const int*)d_in[2];
    const float* W1 = (const float*)d_in[3];
    const float* b1 = (const float*)d_in[4];
    const float* W2 = (const float*)d_in[5];
    const float* b2 = (const float*)d_in[6];
    const float* U1 = (const float*)d_in[7];
    const float* c1 = (const float*)d_in[8];
    const float* U2 = (const float*)d_in[9];
    const float* c2 = (const float*)d_in[10];
    float* out = (float*)d_out;

    const int n = in_sizes[0] / D;
    const int e = in_sizes[1];

    float* m_ptr = nullptr;
    float* z_ptr = nullptr;
    cudaGetSymbolAddress((void**)&m_ptr, g_m);
    cudaGetSymbolAddress((void**)&z_ptr, g_z);

    // 1) per-node edge-MLP message table: m = relu(relu(y@W1+b1)@W2+b2)
    {
        const int blocks = (n + 7) / 8;
        mlp2_kernel<<<blocks, 256>>>(y, W1, b1, W2, b2, m_ptr, n);
    }

    // 2) zero accumulator
    {
        const int n4 = n * D / 4;
        zero_kernel<<<(n4 + 255) / 256, 256>>>((float4*)z_ptr, n4);
    }

    // 3) scatter-add messages into z
    {
        const long long total = (long long)e * 16;
        const int blocks = (int)((total + 255) / 256);
        scatter_kernel<<<blocks, 256>>>(src, dst, e);
    }

    // 4) node-update MLP: out = relu(relu(z@U1+c1)@U2+c2)
    {
        const int blocks = (n + 7) / 8;
        mlp2_kernel<<<blocks, 256>>>(z_ptr, U1, c1, U2, c2, out, n);
    }
}

// round 2
// speedup vs baseline: 1.9506x; 1.9506x over previous
#include <cuda_runtime.h>

#define D 64
#define NMAX 50000
#define TILE_M 128
#define S_T 132   // padded float stride for transposed smem tiles (16B-aligned rows, ~4-way max conflict)

// Scratch (device globals — no allocation allowed in kernel_launch).
__device__ float g_m[NMAX * D];  // per-node message table
__device__ float g_z[NMAX * D];  // segment-sum accumulator

// Dynamic SMEM layout (floats):
//   Xt  [64][S_T]   transposed input tile  (k-major)
//   H1  [64][S_T]   transposed layer-1 activations
//   W1s [64][64]
//   W2s [64][64]
//   b1s [64], b2s [64]
#define SMEM_FLOATS (2 * 64 * S_T + 2 * 64 * 64 + 128)
#define SMEM_BYTES  (SMEM_FLOATS * 4)

// ---------------------------------------------------------------------------
// Zero the accumulator (float4 stores).
// ---------------------------------------------------------------------------
__global__ void zero_kernel(float4* __restrict__ z, int n4) {
    int i = blockIdx.x * blockDim.x + threadIdx.x;
    if (i < n4) z[i] = make_float4(0.f, 0.f, 0.f, 0.f);
}

// ---------------------------------------------------------------------------
// Fused 2-layer MLP, register-blocked tiled GEMM.
// out = relu(relu(in @ W1 + b1) @ W2 + b2), in/out: [n][64].
// Block: 256 threads, 128-node tile. Thread tile: 8 nodes x 4 cols.
// ---------------------------------------------------------------------------
__global__ __launch_bounds__(256, 2) void mlp2_tiled_kernel(
    const float* __restrict__ in,
    const float* __restrict__ W1, const float* __restrict__ b1,
    const float* __restrict__ W2, const float* __restrict__ b2,
    float* __restrict__ out, int n)
{
    extern __shared__ float smem[];
    float* Xt  = smem;                 // 64 * S_T
    float* H1  = Xt + 64 * S_T;        // 64 * S_T
    float* W1s = H1 + 64 * S_T;        // 4096
    float* W2s = W1s + 4096;           // 4096
    float* b1s = W2s + 4096;           // 64
    float* b2s = b1s + 64;             // 64

    const int tid = threadIdx.x;
    const int m0  = blockIdx.x * TILE_M;

    // ---- stage weights + biases ----
#pragma unroll
    for (int p = tid; p < 1024; p += 256) {
        ((float4*)W1s)[p] = ((const float4*)W1)[p];
        ((float4*)W2s)[p] = ((const float4*)W2)[p];
    }
    if (tid < 64) {
        b1s[tid] = b1[tid];
        b2s[tid] = b2[tid];
    }

    // ---- stage X tile, transposed: Xt[k][m] ----
#pragma unroll
    for (int p = tid; p < TILE_M * 16; p += 256) {
        const int m  = p >> 4;        // 0..127
        const int kq = p & 15;        // float4 index along k
        float4 v = make_float4(0.f, 0.f, 0.f, 0.f);
        if (m0 + m < n) v = ((const float4*)in)[(size_t)(m0 + m) * 16 + kq];
        const int k = kq * 4;
        Xt[(k + 0) * S_T + m] = v.x;
        Xt[(k + 1) * S_T + m] = v.y;
        Xt[(k + 2) * S_T + m] = v.z;
        Xt[(k + 3) * S_T + m] = v.w;
    }
    __syncthreads();

    const int tn = tid & 15;          // col group: cols = tn*4 .. tn*4+3
    const int tm = tid >> 4;          // node group: nodes = tm*8 .. tm*8+7
    const int cbase = tn * 4;
    const int mbase = tm * 8;

    float acc[4][8];                  // [col][node]

    // ================= Layer 1 =================
#pragma unroll
    for (int j = 0; j < 4; j++)
#pragma unroll
        for (int i = 0; i < 8; i++) acc[j][i] = 0.f;

#pragma unroll 8
    for (int k = 0; k < 64; k++) {
        const float4 a0 = *(const float4*)&Xt[k * S_T + mbase];
        const float4 a1 = *(const float4*)&Xt[k * S_T + mbase + 4];
        const float4 b  = *(const float4*)&W1s[k * 64 + cbase];
        const float a[8] = {a0.x, a0.y, a0.z, a0.w, a1.x, a1.y, a1.z, a1.w};
        const float bb[4] = {b.x, b.y, b.z, b.w};
#pragma unroll
        for (int j = 0; j < 4; j++)
#pragma unroll
            for (int i = 0; i < 8; i++)
                acc[j][i] = fmaf(a[i], bb[j], acc[j][i]);
    }

    // bias + relu, store transposed into H1[k][m]
#pragma unroll
    for (int j = 0; j < 4; j++) {
        const float bj = b1s[cbase + j];
#pragma unroll
        for (int i = 0; i < 8; i++) acc[j][i] = fmaxf(acc[j][i] + bj, 0.f);
        *(float4*)&H1[(cbase + j) * S_T + mbase] =
            make_float4(acc[j][0], acc[j][1], acc[j][2], acc[j][3]);
        *(float4*)&H1[(cbase + j) * S_T + mbase + 4] =
            make_float4(acc[j][4], acc[j][5], acc[j][6], acc[j][7]);
    }
    __syncthreads();

    // ================= Layer 2 =================
#pragma unroll
    for (int j = 0; j < 4; j++)
#pragma unroll
        for (int i = 0; i < 8; i++) acc[j][i] = 0.f;

#pragma unroll 8
    for (int k = 0; k < 64; k++) {
        const float4 a0 = *(const float4*)&H1[k * S_T + mbase];
        const float4 a1 = *(const float4*)&H1[k * S_T + mbase + 4];
        const float4 b  = *(const float4*)&W2s[k * 64 + cbase];
        const float a[8] = {a0.x, a0.y, a0.z, a0.w, a1.x, a1.y, a1.z, a1.w};
        const float bb[4] = {b.x, b.y, b.z, b.w};
#pragma unroll
        for (int j = 0; j < 4; j++)
#pragma unroll
            for (int i = 0; i < 8; i++)
                acc[j][i] = fmaf(a[i], bb[j], acc[j][i]);
    }

    // bias + relu, coalesced float4 store to gmem
#pragma unroll
    for (int j = 0; j < 4; j++) {
        const float bj = b2s[cbase + j];
#pragma unroll
        for (int i = 0; i < 8; i++) acc[j][i] = fmaxf(acc[j][i] + bj, 0.f);
    }
#pragma unroll
    for (int i = 0; i < 8; i++) {
        const int m = m0 + mbase + i;
        if (m < n)
            *(float4*)&out[(size_t)m * 64 + cbase] =
                make_float4(acc[0][i], acc[1][i], acc[2][i], acc[3][i]);
    }
}

// ---------------------------------------------------------------------------
// Scatter-add: z[dst[e]] += m[src[e]] for all edges.
// 16 threads per edge, one red.global.add.v4.f32 each (coalesced 256B/edge).
// ---------------------------------------------------------------------------
__global__ __launch_bounds__(256) void scatter_kernel(
    const int* __restrict__ src, const int* __restrict__ dst, int e)
{
    const long long idx = (long long)blockIdx.x * blockDim.x + threadIdx.x;
    const int edge = (int)(idx >> 4);
    const int c = (int)(idx & 15);
    if (edge >= e) return;

    const int s = src[edge];
    const int d = dst[edge];

    const float4 v = ((const float4*)g_m)[s * 16 + c];
    float* addr = g_z + (size_t)d * D + c * 4;
    asm volatile("red.global.add.v4.f32 [%0], {%1,%2,%3,%4};"
                 :: "l"(addr), "f"(v.x), "f"(v.y), "f"(v.z), "f"(v.w)
                 : "memory");
}

// ---------------------------------------------------------------------------
extern "C" void kernel_launch(void* const* d_in, const int* in_sizes, int n_in,
                              void* d_out, int out_size) {
    const float* y   = (const float*)d_in[0];
    const int*   src = (const int*)d_in[1];
    const int*   dst = (const int*)d_in[2];
    const float* W1  = (const float*)d_in[3];
    const float* b1  = (const float*)d_in[4];
    const float* W2  = (const float*)d_in[5];
    const float* b2  = (const float*)d_in[6];
    const float* U1  = (const float*)d_in[7];
    const float* c1  = (const float*)d_in[8];
    const float* U2  = (const float*)d_in[9];
    const float* c2  = (const float*)d_in[10];
    float* out = (float*)d_out;

    const int n = in_sizes[0] / D;
    const int e = in_sizes[1];

    float* m_ptr = nullptr;
    float* z_ptr = nullptr;
    cudaGetSymbolAddress((void**)&m_ptr, g_m);
    cudaGetSymbolAddress((void**)&z_ptr, g_z);

    cudaFuncSetAttribute(mlp2_tiled_kernel,
                         cudaFuncAttributeMaxDynamicSharedMemorySize, SMEM_BYTES);

    const int mlp_blocks = (n + TILE_M - 1) / TILE_M;

    // 1) zero accumulator (independent, cheap)
    {
        const int n4 = n * D / 4;
        zero_kernel<<<(n4 + 255) / 256, 256>>>((float4*)z_ptr, n4);
    }

    // 2) per-node edge-MLP message table: m = relu(relu(y@W1+b1)@W2+b2)
    mlp2_tiled_kernel<<<mlp_blocks, 256, SMEM_BYTES>>>(y, W1, b1, W2, b2, m_ptr, n);

    // 3) scatter-add messages into z
    {
        const long long total = (long long)e * 16;
        const int blocks = (int)((total + 255) / 256);
        scatter_kernel<<<blocks, 256>>>(src, dst, e);
    }

    // 4) node-update MLP: out = relu(relu(z@U1+c1)@U2+c2)
    mlp2_tiled_kernel<<<mlp_blocks, 256, SMEM_BYTES>>>(z_ptr, U1, c1, U2, c2, out, n);
}

// round 3
// speedup vs baseline: 1.9737x; 1.0119x over previous
#include <cuda_runtime.h>

#define D 64
#define NMAX 50000
#define EMAX 1250000
#define TILE_M 128
#define S_T 132
#define SCAN_CHUNK 1024

// ---------------- device scratch (no allocation allowed) ----------------
__device__ float g_m[NMAX * D];       // per-node message table
__device__ float g_z[NMAX * D];       // segment-sum result
__device__ int   g_hist[NMAX + 1];
__device__ int   g_off[NMAX + 1];     // CSR offsets (exclusive scan of hist)
__device__ int   g_cursor[NMAX];      // running cursors for reorder
__device__ int   g_bsum[64];          // per-chunk sums for hierarchical scan
__device__ int   g_boff[64];          // per-chunk offsets
__device__ int   g_src_sorted[EMAX];  // src ids sorted by dst

#define SMEM_FLOATS (2 * 64 * S_T + 2 * 64 * 64 + 128)
#define SMEM_BYTES  (SMEM_FLOATS * 4)

// ---------------------------------------------------------------------------
// Fused 2-layer MLP, register-blocked tiled GEMM (unchanged from R2).
// ---------------------------------------------------------------------------
__global__ __launch_bounds__(256, 2) void mlp2_tiled_kernel(
    const float* __restrict__ in,
    const float* __restrict__ W1, const float* __restrict__ b1,
    const float* __restrict__ W2, const float* __restrict__ b2,
    float* __restrict__ out, int n)
{
    extern __shared__ float smem[];
    float* Xt  = smem;
    float* H1  = Xt + 64 * S_T;
    float* W1s = H1 + 64 * S_T;
    float* W2s = W1s + 4096;
    float* b1s = W2s + 4096;
    float* b2s = b1s + 64;

    const int tid = threadIdx.x;
    const int m0  = blockIdx.x * TILE_M;

#pragma unroll
    for (int p = tid; p < 1024; p += 256) {
        ((float4*)W1s)[p] = ((const float4*)W1)[p];
        ((float4*)W2s)[p] = ((const float4*)W2)[p];
    }
    if (tid < 64) {
        b1s[tid] = b1[tid];
        b2s[tid] = b2[tid];
    }

#pragma unroll
    for (int p = tid; p < TILE_M * 16; p += 256) {
        const int m  = p >> 4;
        const int kq = p & 15;
        float4 v = make_float4(0.f, 0.f, 0.f, 0.f);
        if (m0 + m < n) v = ((const float4*)in)[(size_t)(m0 + m) * 16 + kq];
        const int k = kq * 4;
        Xt[(k + 0) * S_T + m] = v.x;
        Xt[(k + 1) * S_T + m] = v.y;
        Xt[(k + 2) * S_T + m] = v.z;
        Xt[(k + 3) * S_T + m] = v.w;
    }
    __syncthreads();

    const int tn = tid & 15;
    const int tm = tid >> 4;
    const int cbase = tn * 4;
    const int mbase = tm * 8;

    float acc[4][8];

#pragma unroll
    for (int j = 0; j < 4; j++)
#pragma unroll
        for (int i = 0; i < 8; i++) acc[j][i] = 0.f;

#pragma unroll 8
    for (int k = 0; k < 64; k++) {
        const float4 a0 = *(const float4*)&Xt[k * S_T + mbase];
        const float4 a1 = *(const float4*)&Xt[k * S_T + mbase + 4];
        const float4 b  = *(const float4*)&W1s[k * 64 + cbase];
        const float a[8] = {a0.x, a0.y, a0.z, a0.w, a1.x, a1.y, a1.z, a1.w};
        const float bb[4] = {b.x, b.y, b.z, b.w};
#pragma unroll
        for (int j = 0; j < 4; j++)
#pragma unroll
            for (int i = 0; i < 8; i++)
                acc[j][i] = fmaf(a[i], bb[j], acc[j][i]);
    }

#pragma unroll
    for (int j = 0; j < 4; j++) {
        const float bj = b1s[cbase + j];
#pragma unroll
        for (int i = 0; i < 8; i++) acc[j][i] = fmaxf(acc[j][i] + bj, 0.f);
        *(float4*)&H1[(cbase + j) * S_T + mbase] =
            make_float4(acc[j][0], acc[j][1], acc[j][2], acc[j][3]);
        *(float4*)&H1[(cbase + j) * S_T + mbase + 4] =
            make_float4(acc[j][4], acc[j][5], acc[j][6], acc[j][7]);
    }
    __syncthreads();

#pragma unroll
    for (int j = 0; j < 4; j++)
#pragma unroll
        for (int i = 0; i < 8; i++) acc[j][i] = 0.f;

#pragma unroll 8
    for (int k = 0; k < 64; k++) {
        const float4 a0 = *(const float4*)&H1[k * S_T + mbase];
        const float4 a1 = *(const float4*)&H1[k * S_T + mbase + 4];
        const float4 b  = *(const float4*)&W2s[k * 64 + cbase];
        const float a[8] = {a0.x, a0.y, a0.z, a0.w, a1.x, a1.y, a1.z, a1.w};
        const float bb[4] = {b.x, b.y, b.z, b.w};
#pragma unroll
        for (int j = 0; j < 4; j++)
#pragma unroll
            for (int i = 0; i < 8; i++)
                acc[j][i] = fmaf(a[i], bb[j], acc[j][i]);
    }

#pragma unroll
    for (int j = 0; j < 4; j++) {
        const float bj = b2s[cbase + j];
#pragma unroll
        for (int i = 0; i < 8; i++) acc[j][i] = fmaxf(acc[j][i] + bj, 0.f);
    }
#pragma unroll
    for (int i = 0; i < 8; i++) {
        const int m = m0 + mbase + i;
        if (m < n)
            *(float4*)&out[(size_t)m * 64 + cbase] =
                make_float4(acc[0][i], acc[1][i], acc[2][i], acc[3][i]);
    }
}

// ---------------------------------------------------------------------------
// Counting sort by dst: histogram -> scan -> reorder.
// ---------------------------------------------------------------------------
__global__ __launch_bounds__(256) void hist_kernel(const int* __restrict__ dst, int e) {
    int i = blockIdx.x * blockDim.x + threadIdx.x;
    if (i < e) {
        int* addr = &g_hist[dst[i]];
        asm volatile("red.global.add.s32 [%0], 1;" :: "l"(addr) : "memory");
    }
}

__device__ __forceinline__ int warp_incl_scan(int v, int lane) {
#pragma unroll
    for (int d = 1; d < 32; d <<= 1) {
        int t = __shfl_up_sync(0xffffffffu, v, d);
        if (lane >= d) v += t;
    }
    return v;
}

// per-chunk sums
__global__ __launch_bounds__(SCAN_CHUNK) void scan_sums_kernel(int n) {
    __shared__ int wsum[32];
    const int g = blockIdx.x * SCAN_CHUNK + threadIdx.x;
    const int lane = threadIdx.x & 31;
    const int wid = threadIdx.x >> 5;
    int x = (g < n) ? g_hist[g] : 0;
#pragma unroll
    for (int d = 16; d > 0; d >>= 1) x += __shfl_down_sync(0xffffffffu, x, d);
    if (lane == 0) wsum[wid] = x;
    __syncthreads();
    if (wid == 0) {
        int v = wsum[lane];
#pragma unroll
        for (int d = 16; d > 0; d >>= 1) v += __shfl_down_sync(0xffffffffu, v, d);
        if (lane == 0) g_bsum[blockIdx.x] = v;
    }
}

// exclusive scan of chunk sums (nb <= 64), also writes g_off[n] = total
__global__ __launch_bounds__(64) void scan_tops_kernel(int nb, int n) {
    const int lane = threadIdx.x & 31;
    const int i = threadIdx.x;
    __shared__ int w0sum;
    int x = (i < nb) ? g_bsum[i] : 0;
    int incl = warp_incl_scan(x, lane);
    if (i == 31) w0sum = incl;
    __syncthreads();
    int excl = incl - x + ((i >= 32) ? w0sum : 0);
    if (i < nb) g_boff[i] = excl;
    if (i == nb - 1) g_off[n] = excl + x;
}

// full exclusive scan, writes g_off and g_cursor
__global__ __launch_bounds__(SCAN_CHUNK) void scan_final_kernel(int n) {
    __shared__ int wsum[32];
    const int g = blockIdx.x * SCAN_CHUNK + threadIdx.x;
    const int lane = threadIdx.x & 31;
    const int wid = threadIdx.x >> 5;
    int x = (g < n) ? g_hist[g] : 0;
    int incl = warp_incl_scan(x, lane);
    if (lane == 31) wsum[wid] = incl;
    __syncthreads();
    if (wid == 0) wsum[lane] = warp_incl_scan(wsum[lane], lane);
    __syncthreads();
    int excl = incl - x + ((wid > 0) ? wsum[wid - 1] : 0) + g_boff[blockIdx.x];
    if (g < n) {
        g_off[g] = excl;
        g_cursor[g] = excl;
    }
}

__global__ __launch_bounds__(256) void reorder_kernel(
    const int* __restrict__ src, const int* __restrict__ dst, int e)
{
    int i = blockIdx.x * blockDim.x + threadIdx.x;
    if (i < e) {
        int pos = atomicAdd(&g_cursor[dst[i]], 1);
        g_src_sorted[pos] = src[i];
    }
}

// ---------------------------------------------------------------------------
// CSR aggregation: warp per node, registers accumulate 64 cols (2/lane),
// single coalesced write. No atomics, z fully written (zeros included).
// ---------------------------------------------------------------------------
__global__ __launch_bounds__(256) void aggregate_kernel(
    const float2* __restrict__ m2, float2* __restrict__ z2, int n)
{
    const int warp = (blockIdx.x * 256 + threadIdx.x) >> 5;
    const int lane = threadIdx.x & 31;
    if (warp >= n) return;

    const int s0 = g_off[warp];
    const int s1 = g_off[warp + 1];

    float ax = 0.f, ay = 0.f;
    for (int base = s0; base < s1; base += 32) {
        const int cnt = min(32, s1 - base);
        int si = (lane < cnt) ? g_src_sorted[base + lane] : 0;
#pragma unroll 4
        for (int j = 0; j < cnt; j++) {
            const int s = __shfl_sync(0xffffffffu, si, j);
            const float2 v = __ldg(&m2[(size_t)s * 32 + lane]);
            ax += v.x;
            ay += v.y;
        }
    }
    float2 o;
    o.x = ax;
    o.y = ay;
    z2[(size_t)warp * 32 + lane] = o;
}

// ---------------------------------------------------------------------------
extern "C" void kernel_launch(void* const* d_in, const int* in_sizes, int n_in,
                              void* d_out, int out_size) {
    const float* y   = (const float*)d_in[0];
    const int*   src = (const int*)d_in[1];
    const int*   dst = (const int*)d_in[2];
    const float* W1  = (const float*)d_in[3];
    const float* b1  = (const float*)d_in[4];
    const float* W2  = (const float*)d_in[5];
    const float* b2  = (const float*)d_in[6];
    const float* U1  = (const float*)d_in[7];
    const float* c1  = (const float*)d_in[8];
    const float* U2  = (const float*)d_in[9];
    const float* c2  = (const float*)d_in[10];
    float* out = (float*)d_out;

    const int n = in_sizes[0] / D;
    const int e = in_sizes[1];

    float* m_ptr = nullptr;
    float* z_ptr = nullptr;
    int*   hist_ptr = nullptr;
    cudaGetSymbolAddress((void**)&m_ptr, g_m);
    cudaGetSymbolAddress((void**)&z_ptr, g_z);
    cudaGetSymbolAddress((void**)&hist_ptr, g_hist);

    cudaFuncSetAttribute(mlp2_tiled_kernel,
                         cudaFuncAttributeMaxDynamicSharedMemorySize, SMEM_BYTES);

    const int mlp_blocks = (n + TILE_M - 1) / TILE_M;
    const int nb = (n + SCAN_CHUNK - 1) / SCAN_CHUNK;

    // --- sort pipeline (independent of mlp1) ---
    cudaMemsetAsync(hist_ptr, 0, (size_t)(n + 1) * sizeof(int));
    hist_kernel<<<(e + 255) / 256, 256>>>(dst, e);

    // overlap-ish: mlp1 queued here (same stream, but keeps GPU busy between
    // small sort kernels' tails)
    mlp2_tiled_kernel<<<mlp_blocks, 256, SMEM_BYTES>>>(y, W1, b1, W2, b2, m_ptr, n);

    scan_sums_kernel<<<nb, SCAN_CHUNK>>>(n);
    scan_tops_kernel<<<1, 64>>>(nb, n);
    scan_final_kernel<<<nb, SCAN_CHUNK>>>(n);
    reorder_kernel<<<(e + 255) / 256, 256>>>(src, dst, e);

    // --- aggregation (needs m + sorted edges) ---
    {
        const int warps = n;
        const int blocks = (warps * 32 + 255) / 256;
        aggregate_kernel<<<blocks, 256>>>((const float2*)m_ptr, (float2*)z_ptr, n);
    }

    // --- node-update MLP ---
    mlp2_tiled_kernel<<<mlp_blocks, 256, SMEM_BYTES>>>(z_ptr, U1, c1, U2, c2, out, n);
}

// round 4
// speedup vs baseline: 2.1651x; 1.0969x over previous
#include <cuda_runtime.h>
#include <cuda_fp16.h>

#define D 64
#define NMAX 50000
#define EMAX 1250000
#define TILE_M 128
#define S_T 132
#define SCAN_CHUNK 1024

// ---------------- device scratch (no allocation allowed) ----------------
__device__ __half g_mh[NMAX * D];     // per-node message table (fp16)
__device__ float  g_z[NMAX * D];      // segment-sum result (fp32)
__device__ int    g_hist[NMAX + 1];
__device__ int    g_off[NMAX + 1];    // CSR offsets
__device__ int    g_cursor[NMAX];
__device__ int    g_bsum[64];
__device__ int    g_boff[64];
__device__ int    g_src_sorted[EMAX];

// Dynamic SMEM (floats): XH[64][S_T] (shared between Xt and H1), W1s, W2s, b1s, b2s
#define SMEM_FLOATS (64 * S_T + 2 * 64 * 64 + 128)
#define SMEM_BYTES  (SMEM_FLOATS * 4)

// ---------------------------------------------------------------------------
// Fused 2-layer MLP, register-blocked tiled GEMM. XH buffer reused for both
// the transposed input tile and the transposed layer-1 activations.
// OutT = float (fp32 rows) or __half (fp16 rows).
// ---------------------------------------------------------------------------
template <typename OutT>
__global__ __launch_bounds__(256, 3) void mlp2_tiled_kernel(
    const float* __restrict__ in,
    const float* __restrict__ W1, const float* __restrict__ b1,
    const float* __restrict__ W2, const float* __restrict__ b2,
    OutT* __restrict__ out, int n)
{
    extern __shared__ float smem[];
    float* XH  = smem;                 // 64 * S_T
    float* W1s = XH + 64 * S_T;        // 4096
    float* W2s = W1s + 4096;           // 4096
    float* b1s = W2s + 4096;           // 64
    float* b2s = b1s + 64;             // 64

    const int tid = threadIdx.x;
    const int m0  = blockIdx.x * TILE_M;

#pragma unroll
    for (int p = tid; p < 1024; p += 256) {
        ((float4*)W1s)[p] = ((const float4*)W1)[p];
        ((float4*)W2s)[p] = ((const float4*)W2)[p];
    }
    if (tid < 64) {
        b1s[tid] = b1[tid];
        b2s[tid] = b2[tid];
    }

    // stage X tile transposed: XH[k][m]
#pragma unroll
    for (int p = tid; p < TILE_M * 16; p += 256) {
        const int m  = p >> 4;
        const int kq = p & 15;
        float4 v = make_float4(0.f, 0.f, 0.f, 0.f);
        if (m0 + m < n) v = ((const float4*)in)[(size_t)(m0 + m) * 16 + kq];
        const int k = kq * 4;
        XH[(k + 0) * S_T + m] = v.x;
        XH[(k + 1) * S_T + m] = v.y;
        XH[(k + 2) * S_T + m] = v.z;
        XH[(k + 3) * S_T + m] = v.w;
    }
    __syncthreads();

    const int tn = tid & 15;
    const int tm = tid >> 4;
    const int cbase = tn * 4;
    const int mbase = tm * 8;

    float acc[4][8];

    // ================= Layer 1 =================
#pragma unroll
    for (int j = 0; j < 4; j++)
#pragma unroll
        for (int i = 0; i < 8; i++) acc[j][i] = 0.f;

#pragma unroll 8
    for (int k = 0; k < 64; k++) {
        const float4 a0 = *(const float4*)&XH[k * S_T + mbase];
        const float4 a1 = *(const float4*)&XH[k * S_T + mbase + 4];
        const float4 b  = *(const float4*)&W1s[k * 64 + cbase];
        const float a[8] = {a0.x, a0.y, a0.z, a0.w, a1.x, a1.y, a1.z, a1.w};
        const float bb[4] = {b.x, b.y, b.z, b.w};
#pragma unroll
        for (int j = 0; j < 4; j++)
#pragma unroll
            for (int i = 0; i < 8; i++)
                acc[j][i] = fmaf(a[i], bb[j], acc[j][i]);
    }

    __syncthreads();   // everyone done READING XH before it is overwritten

    // bias + relu, write H1 transposed back into XH
#pragma unroll
    for (int j = 0; j < 4; j++) {
        const float bj = b1s[cbase + j];
#pragma unroll
        for (int i = 0; i < 8; i++) acc[j][i] = fmaxf(acc[j][i] + bj, 0.f);
        *(float4*)&XH[(cbase + j) * S_T + mbase] =
            make_float4(acc[j][0], acc[j][1], acc[j][2], acc[j][3]);
        *(float4*)&XH[(cbase + j) * S_T + mbase + 4] =
            make_float4(acc[j][4], acc[j][5], acc[j][6], acc[j][7]);
    }
    __syncthreads();

    // ================= Layer 2 =================
#pragma unroll
    for (int j = 0; j < 4; j++)
#pragma unroll
        for (int i = 0; i < 8; i++) acc[j][i] = 0.f;

#pragma unroll 8
    for (int k = 0; k < 64; k++) {
        const float4 a0 = *(const float4*)&XH[k * S_T + mbase];
        const float4 a1 = *(const float4*)&XH[k * S_T + mbase + 4];
        const float4 b  = *(const float4*)&W2s[k * 64 + cbase];
        const float a[8] = {a0.x, a0.y, a0.z, a0.w, a1.x, a1.y, a1.z, a1.w};
        const float bb[4] = {b.x, b.y, b.z, b.w};
#pragma unroll
        for (int j = 0; j < 4; j++)
#pragma unroll
            for (int i = 0; i < 8; i++)
                acc[j][i] = fmaf(a[i], bb[j], acc[j][i]);
    }

#pragma unroll
    for (int j = 0; j < 4; j++) {
        const float bj = b2s[cbase + j];
#pragma unroll
        for (int i = 0; i < 8; i++) acc[j][i] = fmaxf(acc[j][i] + bj, 0.f);
    }

#pragma unroll
    for (int i = 0; i < 8; i++) {
        const int m = m0 + mbase + i;
        if (m < n) {
            if constexpr (sizeof(OutT) == 4) {
                *(float4*)&out[(size_t)m * 64 + cbase] =
                    make_float4(acc[0][i], acc[1][i], acc[2][i], acc[3][i]);
            } else {
                __half2 h01 = __floats2half2_rn(acc[0][i], acc[1][i]);
                __half2 h23 = __floats2half2_rn(acc[2][i], acc[3][i]);
                uint2 u;
                u.x = *(unsigned int*)&h01;
                u.y = *(unsigned int*)&h23;
                *(uint2*)&out[(size_t)m * 64 + cbase] = u;
            }
        }
    }
}

// ---------------------------------------------------------------------------
// Counting sort by dst: histogram -> scan -> reorder.
// ---------------------------------------------------------------------------
__global__ __launch_bounds__(256) void hist_kernel(const int* __restrict__ dst, int e) {
    int i = blockIdx.x * blockDim.x + threadIdx.x;
    if (i < e) {
        int* addr = &g_hist[dst[i]];
        asm volatile("red.global.add.s32 [%0], 1;" :: "l"(addr) : "memory");
    }
}

__device__ __forceinline__ int warp_incl_scan(int v, int lane) {
#pragma unroll
    for (int d = 1; d < 32; d <<= 1) {
        int t = __shfl_up_sync(0xffffffffu, v, d);
        if (lane >= d) v += t;
    }
    return v;
}

__global__ __launch_bounds__(SCAN_CHUNK) void scan_sums_kernel(int n) {
    __shared__ int wsum[32];
    const int g = blockIdx.x * SCAN_CHUNK + threadIdx.x;
    const int lane = threadIdx.x & 31;
    const int wid = threadIdx.x >> 5;
    int x = (g < n) ? g_hist[g] : 0;
#pragma unroll
    for (int d = 16; d > 0; d >>= 1) x += __shfl_down_sync(0xffffffffu, x, d);
    if (lane == 0) wsum[wid] = x;
    __syncthreads();
    if (wid == 0) {
        int v = wsum[lane];
#pragma unroll
        for (int d = 16; d > 0; d >>= 1) v += __shfl_down_sync(0xffffffffu, v, d);
        if (lane == 0) g_bsum[blockIdx.x] = v;
    }
}

__global__ __launch_bounds__(64) void scan_tops_kernel(int nb, int n) {
    const int lane = threadIdx.x & 31;
    const int i = threadIdx.x;
    __shared__ int w0sum;
    int x = (i < nb) ? g_bsum[i] : 0;
    int incl = warp_incl_scan(x, lane);
    if (i == 31) w0sum = incl;
    __syncthreads();
    int excl = incl - x + ((i >= 32) ? w0sum : 0);
    if (i < nb) g_boff[i] = excl;
    if (i == nb - 1) g_off[n] = excl + x;
}

__global__ __launch_bounds__(SCAN_CHUNK) void scan_final_kernel(int n) {
    __shared__ int wsum[32];
    const int g = blockIdx.x * SCAN_CHUNK + threadIdx.x;
    const int lane = threadIdx.x & 31;
    const int wid = threadIdx.x >> 5;
    int x = (g < n) ? g_hist[g] : 0;
    int incl = warp_incl_scan(x, lane);
    if (lane == 31) wsum[wid] = incl;
    __syncthreads();
    if (wid == 0) wsum[lane] = warp_incl_scan(wsum[lane], lane);
    __syncthreads();
    int excl = incl - x + ((wid > 0) ? wsum[wid - 1] : 0) + g_boff[blockIdx.x];
    if (g < n) {
        g_off[g] = excl;
        g_cursor[g] = excl;
    }
}

__global__ __launch_bounds__(256) void reorder_kernel(
    const int* __restrict__ src, const int* __restrict__ dst, int e)
{
    int i = blockIdx.x * blockDim.x + threadIdx.x;
    if (i < e) {
        int pos = atomicAdd(&g_cursor[dst[i]], 1);
        g_src_sorted[pos] = src[i];
    }
}

// ---------------------------------------------------------------------------
// CSR aggregation: warp per node, fp16 gather, fp32 register accumulation.
// ---------------------------------------------------------------------------
__global__ __launch_bounds__(256) void aggregate_kernel(
    const __half2* __restrict__ m2, float2* __restrict__ z2, int n)
{
    const int warp = (blockIdx.x * 256 + threadIdx.x) >> 5;
    const int lane = threadIdx.x & 31;
    if (warp >= n) return;

    const int s0 = g_off[warp];
    const int s1 = g_off[warp + 1];

    float ax = 0.f, ay = 0.f;
    for (int base = s0; base < s1; base += 32) {
        const int cnt = min(32, s1 - base);
        int si = (lane < cnt) ? g_src_sorted[base + lane] : 0;
#pragma unroll 4
        for (int j = 0; j < cnt; j++) {
            const int s = __shfl_sync(0xffffffffu, si, j);
            const __half2 h = __ldg(&m2[(size_t)s * 32 + lane]);
            const float2 v = __half22float2(h);
            ax += v.x;
            ay += v.y;
        }
    }
    float2 o;
    o.x = ax;
    o.y = ay;
    z2[(size_t)warp * 32 + lane] = o;
}

// ---------------------------------------------------------------------------
extern "C" void kernel_launch(void* const* d_in, const int* in_sizes, int n_in,
                              void* d_out, int out_size) {
    const float* y   = (const float*)d_in[0];
    const int*   src = (const int*)d_in[1];
    const int*   dst = (const int*)d_in[2];
    const float* W1  = (const float*)d_in[3];
    const float* b1  = (const float*)d_in[4];
    const float* W2  = (const float*)d_in[5];
    const float* b2  = (const float*)d_in[6];
    const float* U1  = (const float*)d_in[7];
    const float* c1  = (const float*)d_in[8];
    const float* U2  = (const float*)d_in[9];
    const float* c2  = (const float*)d_in[10];
    float* out = (float*)d_out;

    const int n = in_sizes[0] / D;
    const int e = in_sizes[1];

    __half* mh_ptr = nullptr;
    float*  z_ptr  = nullptr;
    int*    hist_ptr = nullptr;
    cudaGetSymbolAddress((void**)&mh_ptr, g_mh);
    cudaGetSymbolAddress((void**)&z_ptr, g_z);
    cudaGetSymbolAddress((void**)&hist_ptr, g_hist);

    cudaFuncSetAttribute(mlp2_tiled_kernel<__half>,
                         cudaFuncAttributeMaxDynamicSharedMemorySize, SMEM_BYTES);
    cudaFuncSetAttribute(mlp2_tiled_kernel<float>,
                         cudaFuncAttributeMaxDynamicSharedMemorySize, SMEM_BYTES);

    // Side stream + events for fork/join inside graph capture.
    // Created once (first, uncaptured correctness call); reused during capture.
    static cudaStream_t s_side = ([] {
        cudaStream_t s;
        cudaStreamCreateWithFlags(&s, cudaStreamNonBlocking);
        return s;
    })();
    static cudaEvent_t ev_fork = ([] {
        cudaEvent_t ev;
        cudaEventCreateWithFlags(&ev, cudaEventDisableTiming);
        return ev;
    })();
    static cudaEvent_t ev_join = ([] {
        cudaEvent_t ev;
        cudaEventCreateWithFlags(&ev, cudaEventDisableTiming);
        return ev;
    })();

    const int mlp_blocks = (n + TILE_M - 1) / TILE_M;
    const int nb = (n + SCAN_CHUNK - 1) / SCAN_CHUNK;

    // ---- fork: sort pipeline on side stream (depends only on src/dst) ----
    cudaEventRecord(ev_fork, (cudaStream_t)0);
    cudaStreamWaitEvent(s_side, ev_fork, 0);

    cudaMemsetAsync(hist_ptr, 0, (size_t)(n + 1) * sizeof(int), s_side);
    hist_kernel<<<(e + 255) / 256, 256, 0, s_side>>>(dst, e);
    scan_sums_kernel<<<nb, SCAN_CHUNK, 0, s_side>>>(n);
    scan_tops_kernel<<<1, 64, 0, s_side>>>(nb, n);
    scan_final_kernel<<<nb, SCAN_CHUNK, 0, s_side>>>(n);
    reorder_kernel<<<(e + 255) / 256, 256, 0, s_side>>>(src, dst, e);
    cudaEventRecord(ev_join, s_side);

    // ---- main stream: edge-MLP message table (fp16 out), overlapped ----
    mlp2_tiled_kernel<__half><<<mlp_blocks, 256, SMEM_BYTES>>>(
        y, W1, b1, W2, b2, mh_ptr, n);

    // ---- join, then aggregate + node MLP ----
    cudaStreamWaitEvent((cudaStream_t)0, ev_join, 0);
    {
        const int blocks = (n * 32 + 255) / 256;
        aggregate_kernel<<<blocks, 256>>>((const __half2*)mh_ptr, (float2*)z_ptr, n);
    }
    mlp2_tiled_kernel<float><<<mlp_blocks, 256, SMEM_BYTES>>>(
        z_ptr, U1, c1, U2, c2, out, n);
}